// round 17
// baseline (speedup 1.0000x reference)
#include <cuda_runtime.h>
#include <cuda_fp16.h>
#include <stdint.h>

// NeuralODE RK4, round 17: fp16/2-pass (R16) with gemm2 rebuilt as 4 intra-CTA
// k-groups x 4 warps, each running gemm1's exact warp economy (64x16 warp tile,
// 8 accumulators, 16 MMAs per 6 ldsm) over K=256. smem 192KB, named barriers
// per group, fixed-order smem reduction + RK4 on group 0.
// 2 kernels/eval = 794 graph nodes (teardown-safe shape).

typedef unsigned int u32;

#define B_DIM 2048
#define F_DIM 256
#define H_DIM 1024
#define BF    (B_DIM * F_DIM)

__device__ __half gA  [BF];                    // xe fp16
__device__ __half gH  [B_DIM * H_DIM];         // h  fp16
__device__ __half gW1a[F_DIM * H_DIM];         // W1 body hi [k][n]
__device__ __half gW1b[F_DIM * H_DIM];         // W1 body lo
__device__ __half gW2a[H_DIM * F_DIM];         // W2 hi      [k][n]
__device__ __half gW2b[H_DIM * F_DIM];         // W2 lo
__device__ float g_xc [BF];                    // RK4 base state
__device__ float g_acc[BF];                    // RK4 k-accumulator

__device__ __forceinline__ u32 s2u(const void* p) {
    u32 a;
    asm("{ .reg .u64 t; cvta.to.shared.u64 t, %1; cvt.u32.u64 %0, t; }" : "=r"(a) : "l"(p));
    return a;
}
__device__ __forceinline__ void split2h(float v, uint16_t& hi, uint16_t& lo) {
    __half h0 = __float2half_rn(v);
    float r = v - __half2float(h0);
    __half h1 = __float2half_rn(r);
    hi = __half_raw(h0).x;
    lo = __half_raw(h1).x;
}
__device__ __forceinline__ uint16_t h16(float v) {
    return __half_raw(__float2half_rn(v)).x;
}
__device__ __forceinline__ void cpa16(u32 dst, const void* src) {
    asm volatile("cp.async.cg.shared.global [%0], [%1], 16;" :: "r"(dst), "l"(src));
}
__device__ __forceinline__ void cpa_commit() { asm volatile("cp.async.commit_group;" ::: "memory"); }
__device__ __forceinline__ void cpwait1() { asm volatile("cp.async.wait_group 1;" ::: "memory"); }
__device__ __forceinline__ void cpwait0() { asm volatile("cp.async.wait_group 0;" ::: "memory"); }
__device__ __forceinline__ void bar128(int id) {
    asm volatile("bar.sync %0, 128;" :: "r"(id) : "memory");
}

__device__ __forceinline__ void ldsm_a(u32 addr, u32& r0, u32& r1, u32& r2, u32& r3) {
    asm volatile("ldmatrix.sync.aligned.m8n8.x4.shared.b16 {%0,%1,%2,%3}, [%4];"
                 : "=r"(r0), "=r"(r1), "=r"(r2), "=r"(r3) : "r"(addr));
}
__device__ __forceinline__ void ldsm_bt(u32 addr, u32& r0, u32& r1, u32& r2, u32& r3) {
    asm volatile("ldmatrix.sync.aligned.m8n8.x4.trans.shared.b16 {%0,%1,%2,%3}, [%4];"
                 : "=r"(r0), "=r"(r1), "=r"(r2), "=r"(r3) : "r"(addr));
}
__device__ __forceinline__ void mma16816(float* c, const u32* a, u32 b0, u32 b1) {
    asm volatile(
        "mma.sync.aligned.m16n8k16.row.col.f32.f16.f16.f32 "
        "{%0,%1,%2,%3}, {%4,%5,%6,%7}, {%8,%9}, {%0,%1,%2,%3};"
        : "+f"(c[0]), "+f"(c[1]), "+f"(c[2]), "+f"(c[3])
        : "r"(a[0]), "r"(a[1]), "r"(a[2]), "r"(a[3]), "r"(b0), "r"(b1));
}

// ---------------- setup ----------------

__global__ void k_conv(const float* __restrict__ W1, const float* __restrict__ W2) {
    int i = blockIdx.x * blockDim.x + threadIdx.x;
    uint16_t a, b;
    if (i < F_DIM * H_DIM) {
        split2h(W1[i], a, b);
        ((uint16_t*)gW1a)[i] = a;
        ((uint16_t*)gW1b)[i] = b;
    } else if (i < 2 * F_DIM * H_DIM) {
        int j = i - F_DIM * H_DIM;
        split2h(W2[j], a, b);
        ((uint16_t*)gW2a)[j] = a;
        ((uint16_t*)gW2b)[j] = b;
    }
}

__global__ void k_init(const float* __restrict__ x, float* __restrict__ out) {
    int i = blockIdx.x * blockDim.x + threadIdx.x;
    if (i >= BF) return;
    float v = x[i];
    out[i] = v;
    g_xc[i] = v;
    ((uint16_t*)gA)[i] = h16(v);
}

// ---------------- GEMM1: h = tanh(xe @ W1x + te*wt + b1) ----------------
// grid (16,16): CTA 128x64, 4 chunks of k64, 2 stages, 2 CTAs/SM.
// smem per stage: A 16K | B0 8K | B1 8K = 32K; x2 = 64K.

#define G1_BUF 32768u

__global__ __launch_bounds__(256, 2) void k_gemm1(const float* __restrict__ b1,
                                                  const float* __restrict__ wt,
                                                  float te) {
    extern __shared__ __align__(128) unsigned char smem[];
    const u32 sb = s2u(smem);
    const int tid = threadIdx.x, lane = tid & 31, wid = tid >> 5;
    const int wm = wid & 1, wn = wid >> 1;            // 2 x 4 warp grid, tile 64x16
    const int m0 = blockIdx.x * 128, n0 = blockIdx.y * 64;

    float acc[4][2][4];
    #pragma unroll
    for (int i = 0; i < 4; ++i)
        #pragma unroll
        for (int j = 0; j < 2; ++j)
            #pragma unroll
            for (int q = 0; q < 4; ++q) acc[i][j][q] = 0.0f;

    auto issue = [&](int c) {
        int ko = c * 64;
        u32 st = sb + (u32)(c & 1) * G1_BUF;
        #pragma unroll
        for (int t = 0; t < 4; ++t) {           // A plane, 128x64 fp16
            int cc = tid + t * 256;
            int r = cc >> 3, col = cc & 7;
            u32 off = (u32)r * 128 + (u32)((col ^ (r & 7)) << 4);
            cpa16(st + off, gA + (size_t)(m0 + r) * F_DIM + ko + col * 8);
        }
        #pragma unroll
        for (int t = 0; t < 2; ++t) {           // B planes, 64x64 each
            int cc = tid + t * 256;
            int r = cc >> 3, col = cc & 7;
            u32 off = (u32)r * 128 + (u32)((col ^ (r & 7)) << 4);
            size_t gsrc = (size_t)(ko + r) * H_DIM + n0 + col * 8;
            cpa16(st + 16384 + off, gW1a + gsrc);
            cpa16(st + 24576 + off, gW1b + gsrc);
        }
        cpa_commit();
    };

    const int lr  = (lane & 7) + ((lane >> 3) & 1) * 8;
    const int hk  = lane >> 4;
    const int ar0 = wm * 64 + lr;
    const int asw = ar0 & 7;
    const int bsw = lr & 7;
    const int nblk = wn * 2 + hk;

    issue(0);
    #pragma unroll 1
    for (int c = 0; c < 4; ++c) {
        if (c + 1 < 4) { issue(c + 1); cpwait1(); } else { cpwait0(); }
        __syncthreads();
        u32 st = sb + (u32)(c & 1) * G1_BUF;
        #pragma unroll
        for (int ks = 0; ks < 4; ++ks) {
            u32 acol = (u32)((((ks << 1) + hk) ^ asw) << 4);
            u32 a[4][4];
            #pragma unroll
            for (int mi = 0; mi < 4; ++mi) {
                u32 rowoff = (u32)(ar0 + mi * 16) * 128 + acol;
                ldsm_a(st + rowoff, a[mi][0], a[mi][1], a[mi][2], a[mi][3]);
            }
            u32 boff = (u32)(ks * 16 + lr) * 128 + (u32)((nblk ^ bsw) << 4);
            u32 b0[2][2], b1v[2][2];
            ldsm_bt(st + 16384 + boff, b0[0][0], b0[0][1], b0[1][0], b0[1][1]);
            ldsm_bt(st + 24576 + boff, b1v[0][0], b1v[0][1], b1v[1][0], b1v[1][1]);
            #pragma unroll
            for (int mi = 0; mi < 4; ++mi)
                #pragma unroll
                for (int nb = 0; nb < 2; ++nb)
                    mma16816(acc[mi][nb], a[mi], b0[nb][0], b0[nb][1]);
            #pragma unroll
            for (int mi = 0; mi < 4; ++mi)
                #pragma unroll
                for (int nb = 0; nb < 2; ++nb)
                    mma16816(acc[mi][nb], a[mi], b1v[nb][0], b1v[nb][1]);
        }
        __syncthreads();
    }

    // epilogue: bias + te*wt, tanh -> single fp16 H plane
    const int rbase = m0 + wm * 64 + (lane >> 2);
    const int cbase = n0 + wn * 16 + (lane & 3) * 2;
    #pragma unroll
    for (int nb = 0; nb < 2; ++nb) {
        int j = cbase + nb * 8;
        float2 bb = *(const float2*)(b1 + j);
        float2 ww = *(const float2*)(wt + j);
        float bias0 = bb.x + te * ww.x;
        float bias1 = bb.y + te * ww.y;
        #pragma unroll
        for (int mi = 0; mi < 4; ++mi) {
            #pragma unroll
            for (int h = 0; h < 2; ++h) {
                int row = rbase + mi * 16 + h * 8;
                float v0 = tanhf(acc[mi][nb][h * 2]     + bias0);
                float v1 = tanhf(acc[mi][nb][h * 2 + 1] + bias1);
                ((u32*)gH)[((size_t)row * H_DIM + j) >> 1] =
                    (u32)h16(v0) | ((u32)h16(v1) << 16);
            }
        }
    }
}

// ---------------- GEMM2 + RK4: k = h @ W2 + b2 ----------------
// grid (32,4), 512 threads = 4 k-groups x 4 warps. Group g: K[g*256,(g+1)*256),
// 4 chunks of k64, warp tile 64x16 (8 accumulators — gemm1 economy), own
// 2-stage pipeline (24KB/stage) + named barrier. smem 192KB, 1 CTA/SM.
// Groups 1-3 spill accs to smem (conflict-free [idx][ltid] layout); group 0
// reduces in fixed order, adds bias, runs the RK4 state machine.

#define G2_BUF 24576u

__global__ __launch_bounds__(512, 1) void k_gemm2(const float* __restrict__ b2,
                                                  float* __restrict__ out,
                                                  int e, int s, float ae) {
    extern __shared__ __align__(128) unsigned char smem[];
    const u32 sb = s2u(smem);
    const int tid  = threadIdx.x;
    const int grp  = tid >> 7;                 // k-group 0..3
    const int ltid = tid & 127;
    const int lane = tid & 31;
    const int lwid = (tid >> 5) & 3;           // warp within group (n-position)
    const int m0 = blockIdx.x * 64, n0 = blockIdx.y * 64;
    const u32 gbase = sb + (u32)grp * (2 * G2_BUF);
    const int kb = grp * 256;
    const int barid = 1 + grp;

    float acc[4][2][4];
    #pragma unroll
    for (int i = 0; i < 4; ++i)
        #pragma unroll
        for (int j = 0; j < 2; ++j)
            #pragma unroll
            for (int q = 0; q < 4; ++q) acc[i][j][q] = 0.0f;

    auto issue = [&](int c) {
        int ko = kb + c * 64;
        u32 st = gbase + (u32)(c & 1) * G2_BUF;
        #pragma unroll
        for (int t = 0; t < 4; ++t) {           // A plane (H), 64x64 fp16 = 8KB
            int cc = ltid + t * 128;
            int r = cc >> 3, col = cc & 7;
            u32 off = (u32)r * 128 + (u32)((col ^ (r & 7)) << 4);
            cpa16(st + off, gH + (size_t)(m0 + r) * H_DIM + ko + col * 8);
        }
        #pragma unroll
        for (int t = 0; t < 4; ++t) {           // B planes (W2), 64x64 each = 8KB
            int cc = ltid + t * 128;
            int r = cc >> 3, col = cc & 7;
            u32 off = (u32)r * 128 + (u32)((col ^ (r & 7)) << 4);
            size_t gsrc = (size_t)(ko + r) * F_DIM + n0 + col * 8;
            cpa16(st + 8192 + off,  gW2a + gsrc);
            cpa16(st + 16384 + off, gW2b + gsrc);
        }
        cpa_commit();
    };

    const int lr  = (lane & 7) + ((lane >> 3) & 1) * 8;
    const int hk  = lane >> 4;
    const int ar0 = lr;                         // warp covers all 64 rows (mi*16)
    const int asw = ar0 & 7;
    const int bsw = lr & 7;
    const int nblk = lwid * 2 + hk;

    issue(0);
    #pragma unroll 1
    for (int c = 0; c < 4; ++c) {
        if (c + 1 < 4) { issue(c + 1); cpwait1(); } else { cpwait0(); }
        bar128(barid);
        u32 st = gbase + (u32)(c & 1) * G2_BUF;
        #pragma unroll
        for (int ks = 0; ks < 4; ++ks) {
            u32 acol = (u32)((((ks << 1) + hk) ^ asw) << 4);
            u32 a[4][4];
            #pragma unroll
            for (int mi = 0; mi < 4; ++mi) {
                u32 rowoff = (u32)(ar0 + mi * 16) * 128 + acol;
                ldsm_a(st + rowoff, a[mi][0], a[mi][1], a[mi][2], a[mi][3]);
            }
            u32 boff = (u32)(ks * 16 + lr) * 128 + (u32)((nblk ^ bsw) << 4);
            u32 b0[2][2], b1v[2][2];
            ldsm_bt(st + 8192 + boff,  b0[0][0], b0[0][1], b0[1][0], b0[1][1]);
            ldsm_bt(st + 16384 + boff, b1v[0][0], b1v[0][1], b1v[1][0], b1v[1][1]);
            #pragma unroll
            for (int mi = 0; mi < 4; ++mi)
                #pragma unroll
                for (int nb = 0; nb < 2; ++nb)
                    mma16816(acc[mi][nb], a[mi], b0[nb][0], b0[nb][1]);
            #pragma unroll
            for (int mi = 0; mi < 4; ++mi)
                #pragma unroll
                for (int nb = 0; nb < 2; ++nb)
                    mma16816(acc[mi][nb], a[mi], b1v[nb][0], b1v[nb][1]);
        }
        bar128(barid);
    }

    // ---- intra-CTA 4-way split-K reduction ----
    __syncthreads();                 // all groups' mainloop smem reads done
    float* red = (float*)smem;       // [32][128] per group: 16KB x3 = 48KB
    if (grp > 0) {
        float* rg = red + (size_t)(grp - 1) * 4096;
        #pragma unroll
        for (int mi = 0; mi < 4; ++mi)
            #pragma unroll
            for (int nb = 0; nb < 2; ++nb)
                #pragma unroll
                for (int q = 0; q < 4; ++q)
                    rg[(mi * 8 + nb * 4 + q) * 128 + ltid] = acc[mi][nb][q];
    }
    __syncthreads();

    if (grp == 0) {
        #pragma unroll
        for (int g = 0; g < 3; ++g) {
            const float* rg = red + (size_t)g * 4096;
            #pragma unroll
            for (int mi = 0; mi < 4; ++mi)
                #pragma unroll
                for (int nb = 0; nb < 2; ++nb)
                    #pragma unroll
                    for (int q = 0; q < 4; ++q)
                        acc[mi][nb][q] += rg[(mi * 8 + nb * 4 + q) * 128 + ltid];
        }

        // epilogue: RK4 state machine (CTA uniquely owns its 64x64 tile)
        const float dt6 = (1.0f / 99.0f) / 6.0f;
        const float be = (e == 1 || e == 2) ? 2.0f : 1.0f;
        const int rbase = m0 + (lane >> 2);
        const int cbase = n0 + lwid * 16 + (lane & 3) * 2;
        #pragma unroll
        for (int nb = 0; nb < 2; ++nb) {
            int j = cbase + nb * 8;
            float2 bb = *(const float2*)(b2 + j);
            #pragma unroll
            for (int mi = 0; mi < 4; ++mi) {
                #pragma unroll
                for (int h = 0; h < 2; ++h) {
                    int row = rbase + mi * 16 + h * 8;
                    size_t go = (size_t)row * F_DIM + j;
                    float kv0 = acc[mi][nb][h * 2]     + bb.x;
                    float kv1 = acc[mi][nb][h * 2 + 1] + bb.y;
                    float2 xcv = *(const float2*)&g_xc[go];
                    float a0, a1;
                    if (e == 0) { a0 = kv0; a1 = kv1; }
                    else {
                        float2 av = *(const float2*)&g_acc[go];
                        a0 = av.x + be * kv0; a1 = av.y + be * kv1;
                    }
                    float x0, x1;
                    if (e < 3) {
                        x0 = xcv.x + ae * kv0; x1 = xcv.y + ae * kv1;
                        *(float2*)&g_acc[go] = make_float2(a0, a1);
                    } else {
                        x0 = xcv.x + dt6 * a0; x1 = xcv.y + dt6 * a1;
                        *(float2*)&g_xc[go] = make_float2(x0, x1);
                        *(float2*)&out[(size_t)(s + 1) * BF + go] = make_float2(x0, x1);
                    }
                    ((u32*)gA)[go >> 1] = (u32)h16(x0) | ((u32)h16(x1) << 16);
                }
            }
        }
    }
}

// ---------------- host ----------------

extern "C" void kernel_launch(void* const* d_in, const int* in_sizes, int n_in,
                              void* d_out, int out_size) {
    (void)in_sizes; (void)n_in; (void)out_size;
    const float* x  = (const float*)d_in[0];
    const float* W1 = (const float*)d_in[1];
    const float* b1 = (const float*)d_in[2];
    const float* W2 = (const float*)d_in[3];
    const float* b2 = (const float*)d_in[4];
    float* out = (float*)d_out;

    cudaFuncSetAttribute(k_gemm1, cudaFuncAttributeMaxDynamicSharedMemorySize, 2 * G1_BUF);
    cudaFuncSetAttribute(k_gemm2, cudaFuncAttributeMaxDynamicSharedMemorySize, 8 * G2_BUF);

    k_conv<<<2048, 256>>>(W1, W2);
    k_init<<<2048, 256>>>(x, out);

    const float dt = 1.0f / 99.0f;
    const float* wt = W1 + (size_t)F_DIM * H_DIM;   // time row of W1
    for (int s = 0; s < 99; ++s) {
        float t0 = s * dt;
        const float te_arr[4] = {t0, t0 + 0.5f * dt, t0 + 0.5f * dt, t0 + dt};
        const float ae_arr[4] = {0.5f * dt, 0.5f * dt, dt, 0.0f};
        for (int e = 0; e < 4; ++e) {
            k_gemm1<<<dim3(16, 16), 256, 2 * G1_BUF>>>(b1, wt, te_arr[e]);
            k_gemm2<<<dim3(32, 4), 512, 8 * G2_BUF>>>(b2, out, e, s, ae_arr[e]);
        }
    }
}